// round 4
// baseline (speedup 1.0000x reference)
#include <cuda_runtime.h>

// DynamicRouting: votes [B=32, NIN=2048, NOUT=64, ATOMS=16] fp32, 3 iterations.
// logits are linear in accumulated pose P:  l = votes . (sum of prior poses)
//
// R4: chunk-major iteration order for L2 residency. B split into 4 chunks of
// 8 batches (64MB votes each, fits the 126MB L2, which persists across kernel
// launches). All 3 iterations run on a chunk back-to-back: iters 2,3 hit L2
// (~2x DRAM bandwidth). Kernel boundaries are the inter-iteration syncs.
// Per-iter preact buffers; each block redundantly derives P from prior preacts
// (no squash kernels between iterations). Iter 0 = uniform c (softmax of 0).

#define NB    32
#define NIN   2048
#define NOUT  64
#define ATOMS 16
#define SLICE (NOUT * ATOMS)   // 1024 floats = 4KB per (b,in)

#define NITER 3
__device__ __align__(256) float g_preact[NITER][NB * SLICE];

#define WARPS_PB      4
#define IN_PER_WARP   8
#define INS_PER_BLOCK (WARPS_PB * IN_PER_WARP)          // 32
#define BLOCKS_PER_B  (NIN / INS_PER_BLOCK)             // 64
#define CHUNK_B       8
#define NCHUNK        (NB / CHUNK_B)                    // 4
#define ROUTE_GRID    (CHUNK_B * BLOCKS_PER_B)          // 512
#define DEPTH         3

__global__ void init_kernel() {
    int idx = blockIdx.x * blockDim.x + threadIdx.x;
    if (idx < NITER * NB * SLICE)
        (&g_preact[0][0])[idx] = 0.0f;
}

__device__ __forceinline__ unsigned smem_u32(const void* p) {
    return (unsigned)__cvta_generic_to_shared(p);
}

// Stage one 4KB slice gmem->smem: 8 x 16B per lane, fully coalesced.
__device__ __forceinline__ void cp_async_slice(unsigned dst, const float4* __restrict__ src,
                                               int lane) {
#pragma unroll
    for (int j = 0; j < 8; j++) {
        asm volatile("cp.async.cg.shared.global [%0], [%1], 16;\n" ::
                     "r"(dst + (unsigned)(lane + 32 * j) * 16u),
                     "l"(src + lane + 32 * j) : "memory");
    }
    asm volatile("cp.async.commit_group;\n" ::: "memory");
}

__device__ __forceinline__ void cp_async_wait(int n) {
    if (n == 0)      asm volatile("cp.async.wait_group 0;\n" ::: "memory");
    else if (n == 1) asm volatile("cp.async.wait_group 1;\n" ::: "memory");
    else             asm volatile("cp.async.wait_group 2;\n" ::: "memory");
}

// Lane layout per slice: lane holds float4 at slice pos 4*lane + 128*j (j=0..7)
// -> out = lane/4 + 8j, atoms 4*(lane&3)..+3.
template <int ITER>
__global__ __launch_bounds__(128, 4) void route_kernel(const float* __restrict__ votes, int b0) {
    __shared__ float stage[WARPS_PB][DEPTH][SLICE];   // 48KB

    const int lane = threadIdx.x & 31;
    const int warp = threadIdx.x >> 5;
    const int b    = b0 + blockIdx.x / BLOCKS_PER_B;
    const int blk  = blockIdx.x % BLOCKS_PER_B;
    const int in0  = (blk * WARPS_PB + warp) * IN_PER_WARP;

    const float4* V = reinterpret_cast<const float4*>(votes)
                      + (size_t)(b * NIN + in0) * (SLICE / 4);

    unsigned sbase[DEPTH];
#pragma unroll
    for (int d = 0; d < DEPTH; d++) sbase[d] = smem_u32(&stage[warp][d][0]);

    // prologue: fill the pipeline
#pragma unroll
    for (int k = 0; k < DEPTH; k++)
        cp_async_slice(sbase[k], V + (size_t)k * (SLICE / 4), lane);

    // Derive P = sum of poses from prior iterations' preact buffers (L2-hot,
    // redundant per block -> no squash kernels / extra syncs needed).
    float4 P[8];
#pragma unroll
    for (int j = 0; j < 8; j++) P[j] = make_float4(0.f, 0.f, 0.f, 0.f);
#pragma unroll
    for (int k = 0; k < ITER; k++) {
        const float4* pre4 = reinterpret_cast<const float4*>(&g_preact[k][b * SLICE]);
#pragma unroll
        for (int j = 0; j < 8; j++) {
            float4 pr = pre4[lane + 32 * j];
            float sq = pr.x * pr.x + pr.y * pr.y + pr.z * pr.z + pr.w * pr.w;
            sq += __shfl_xor_sync(0xffffffffu, sq, 1);
            sq += __shfl_xor_sync(0xffffffffu, sq, 2);
            float scale = (sq / (1.0f + sq)) * rsqrtf(sq + 1e-9f);
            P[j].x = fmaf(scale, pr.x, P[j].x);
            P[j].y = fmaf(scale, pr.y, P[j].y);
            P[j].z = fmaf(scale, pr.z, P[j].z);
            P[j].w = fmaf(scale, pr.w, P[j].w);
        }
    }

    float4 acc[8];
#pragma unroll
    for (int j = 0; j < 8; j++) acc[j] = make_float4(0.f, 0.f, 0.f, 0.f);

#pragma unroll
    for (int i = 0; i < IN_PER_WARP; i++) {
        int rem = IN_PER_WARP - 1 - i;
        cp_async_wait(rem < DEPTH - 1 ? rem : DEPTH - 1);

        const float4* sb = reinterpret_cast<const float4*>(&stage[warp][i % DEPTH][0]);
        float4 v[8];
#pragma unroll
        for (int j = 0; j < 8; j++) v[j] = sb[lane + 32 * j];

        if (i + DEPTH < IN_PER_WARP)
            cp_async_slice(sbase[i % DEPTH], V + (size_t)(i + DEPTH) * (SLICE / 4), lane);

        if (ITER == 0) {
            // softmax(0) = uniform 1/NOUT: plain sum, scale at the end
#pragma unroll
            for (int j = 0; j < 8; j++) {
                acc[j].x += v[j].x; acc[j].y += v[j].y;
                acc[j].z += v[j].z; acc[j].w += v[j].w;
            }
        } else {
            // logits: 16-atom dot via 4-lane xor reduce
            float l[8];
#pragma unroll
            for (int j = 0; j < 8; j++) {
                float d = v[j].x * P[j].x + v[j].y * P[j].y
                        + v[j].z * P[j].z + v[j].w * P[j].w;
                d += __shfl_xor_sync(0xffffffffu, d, 1);
                d += __shfl_xor_sync(0xffffffffu, d, 2);
                l[j] = d;
            }
            // softmax over 64 outs, no max shift (|l| small, fp32-safe)
            float s = 0.f;
#pragma unroll
            for (int j = 0; j < 8; j++) { l[j] = __expf(l[j]); s += l[j]; }
            s += __shfl_xor_sync(0xffffffffu, s, 4);
            s += __shfl_xor_sync(0xffffffffu, s, 8);
            s += __shfl_xor_sync(0xffffffffu, s, 16);
            float inv = 1.0f / s;
#pragma unroll
            for (int j = 0; j < 8; j++) {
                float c = l[j] * inv;
                acc[j].x = fmaf(c, v[j].x, acc[j].x);
                acc[j].y = fmaf(c, v[j].y, acc[j].y);
                acc[j].z = fmaf(c, v[j].z, acc[j].z);
                acc[j].w = fmaf(c, v[j].w, acc[j].w);
            }
        }
    }

    if (ITER == 0) {
        const float u = 1.0f / NOUT;
#pragma unroll
        for (int j = 0; j < 8; j++) {
            acc[j].x *= u; acc[j].y *= u; acc[j].z *= u; acc[j].w *= u;
        }
    }

    // block-level reduce via stage smem (all cp.async retired), then red.v4
    __syncthreads();
    float4* aw = reinterpret_cast<float4*>(&stage[warp][0][0]);
#pragma unroll
    for (int j = 0; j < 8; j++) aw[lane + 32 * j] = acc[j];
    __syncthreads();

#pragma unroll
    for (int q = threadIdx.x; q < SLICE / 4; q += 128) {
        float4 s = make_float4(0.f, 0.f, 0.f, 0.f);
#pragma unroll
        for (int w = 0; w < WARPS_PB; w++) {
            float4 a = reinterpret_cast<const float4*>(&stage[w][0][0])[q];
            s.x += a.x; s.y += a.y; s.z += a.z; s.w += a.w;
        }
        float* out = &g_preact[ITER][b * SLICE + 4 * q];
        asm volatile("red.global.add.v4.f32 [%0], {%1, %2, %3, %4};\n"
                     :: "l"(out), "f"(s.x), "f"(s.y), "f"(s.z), "f"(s.w)
                     : "memory");
    }
}

// Final: pose = squash(preact[last]); outputs pose [B,NOUT,ATOMS] + prob [B,NOUT].
__global__ void final_squash_kernel(float* __restrict__ d_out) {
    int idx = blockIdx.x * blockDim.x + threadIdx.x;  // (b*NOUT + out)
    if (idx >= NB * NOUT) return;

    const float* pre = &g_preact[NITER - 1][idx * ATOMS];
    float s[ATOMS];
    float sq = 0.f;
#pragma unroll
    for (int a = 0; a < ATOMS; a++) { s[a] = pre[a]; sq += s[a] * s[a]; }

    float scale = (sq / (1.0f + sq)) * rsqrtf(sq + 1e-9f);
#pragma unroll
    for (int a = 0; a < ATOMS; a++)
        d_out[idx * ATOMS + a] = s[a] * scale;
    float psq = scale * scale * sq;
    d_out[NB * NOUT * ATOMS + idx] = sqrtf(psq + 1e-9f);
}

extern "C" void kernel_launch(void* const* d_in, const int* in_sizes, int n_in,
                              void* d_out, int out_size) {
    const float* votes = (const float*)d_in[0];
    float* out = (float*)d_out;

    init_kernel<<<(NITER * NB * SLICE + 255) / 256, 256>>>();

    for (int c = 0; c < NCHUNK; c++) {
        int b0 = c * CHUNK_B;
        route_kernel<0><<<ROUTE_GRID, 128>>>(votes, b0);
        route_kernel<1><<<ROUTE_GRID, 128>>>(votes, b0);
        route_kernel<2><<<ROUTE_GRID, 128>>>(votes, b0);
    }
    final_squash_kernel<<<(NB * NOUT + 255) / 256, 256>>>(out);
}